// round 10
// baseline (speedup 1.0000x reference)
#include <cuda_runtime.h>

#define Bn 8
#define Cn 32
#define Hn 512
#define Wn 512
#define On 4
#define TW 64
#define TH 32
#define RR 4
#define SST 66                  // smem row stride (floats), even -> 8B-aligned pairs
#define SROWS (TH + 2)
#define SN (SROWS * SST)        // 2244 floats staged per channel
#define K_LD 9                  // ceil(2244 / 256)
#define NTHREADS 256
#define BN_EPS 1e-5f

typedef unsigned long long ull;

__device__ double g_stats[2 * On];   // [0..3] sum, [4..7] sumsq

__device__ __forceinline__ void fma2(ull& d, ull a, ull b) {
    // packed fp32 fma (sm_100+): d = a*b + d, two lanes per instruction
    asm("fma.rn.f32x2 %0, %1, %2, %0;" : "+l"(d) : "l"(a), "l"(b));
}
__device__ __forceinline__ ull splat2(float f) {
    unsigned u = __float_as_uint(f);
    return ((ull)u << 32) | (ull)u;
}
__device__ __forceinline__ float2 unpack2(ull v) {
    float2 r;
    r.x = __uint_as_float((unsigned)v);
    r.y = __uint_as_float((unsigned)(v >> 32));
    return r;
}

__global__ void zero_stats_kernel() {
    if (threadIdx.x < 2 * On) g_stats[threadIdx.x] = 0.0;
}

// ---------------------------------------------------------------------------
// Pass 1: fused 5-tap stencil (4 directional diffs -> 1x1 conv 4C->4),
// packed f32x2 engine + register-prefetch double buffering of the x tile.
// NOTE: no min-blocks clause -> ptxas must not spill (regs ~112, occ 2).
// ---------------------------------------------------------------------------
__global__ __launch_bounds__(NTHREADS)
void fourdir_main(const float* __restrict__ x,
                  const float* __restrict__ wc_g,
                  float* __restrict__ out)
{
    __shared__ __align__(16) float sx[SN];
    __shared__ __align__(16) ull   swt[Cn][5][On];  // splatted taps NE,NW,SE,SW,C
    __shared__ float s_red[2 * On];

    const int tid = threadIdx.x;
    const int bxw = blockIdx.x;   // w tile (8)
    const int byh = blockIdx.y;   // h tile (16)
    const int bz  = blockIdx.z;   // batch (8)

    // Build combined splatted weights once per block
    if (tid < Cn * On) {
        int c = tid >> 2, o = tid & 3;
        float w0 = wc_g[o * (4 * Cn) + 0 * Cn + c];  // NE
        float w1 = wc_g[o * (4 * Cn) + 1 * Cn + c];  // NW
        float w2 = wc_g[o * (4 * Cn) + 2 * Cn + c];  // SE
        float w3 = wc_g[o * (4 * Cn) + 3 * Cn + c];  // SW
        swt[c][0][o] = splat2(w0);
        swt[c][1][o] = splat2(w1);
        swt[c][2][o] = splat2(w2);
        swt[c][3][o] = splat2(w3);
        swt[c][4][o] = splat2(-(w0 + w1 + w2 + w3)); // center tap
    }
    if (tid < 2 * On) s_red[tid] = 0.0f;

    const int px = tid & 31;       // pair-column index (32 pairs = 64 cols)
    const int gy = tid >> 5;       // row group (8 groups x RR rows = 32 rows)
    const int lw = px << 1;        // local output col (even)
    const int i0 = gy * RR;        // first output row (local)

    const int gh0 = byh * TH - 1;  // global row of smem row 0 (halo)
    const int gw0 = bxw * TW - 1;  // global col of smem col 0 (halo)

    // Precompute staging offsets (loop-invariant across channels)
    int off[K_LD];
#pragma unroll
    for (int k = 0; k < K_LD; ++k) {
        int i = tid + k * NTHREADS;
        int r = i / SST;
        int cl = i - r * SST;
        int gh = gh0 + r;
        int gw = gw0 + cl;
        bool ok = (i < SN) && ((unsigned)gh < (unsigned)Hn) && ((unsigned)gw < (unsigned)Wn);
        off[k] = ok ? (gh * Wn + gw) : -1;
    }

    const float* xb = x + (size_t)bz * Cn * Hn * Wn;

    // Prefetch channel 0 into registers
    float v[K_LD];
#pragma unroll
    for (int k = 0; k < K_LD; ++k)
        v[k] = (off[k] >= 0) ? __ldg(xb + off[k]) : 0.0f;

    ull acc[RR][On];
#pragma unroll
    for (int r2 = 0; r2 < RR; ++r2)
#pragma unroll
        for (int o = 0; o < On; ++o) acc[r2][o] = 0ull;

    const float* bp0 = sx + i0 * SST + lw;

    for (int c = 0; c < Cn; ++c) {
        __syncthreads();   // previous channel's compute done (smem reusable)

        // publish current channel's tile
#pragma unroll
        for (int k = 0; k < K_LD; ++k) {
            int i = tid + k * NTHREADS;
            if (i < SN) sx[i] = v[k];
        }

        // prefetch next channel (last iteration re-reads same plane; unused)
        {
            int cn = (c < Cn - 1) ? (c + 1) : c;
            const float* xn = xb + (size_t)cn * (Hn * Wn);
#pragma unroll
            for (int k = 0; k < K_LD; ++k)
                v[k] = (off[k] >= 0) ? __ldg(xn + off[k]) : 0.0f;
        }

        __syncthreads();   // staging visible

        const ull* wp = &swt[c][0][0];   // broadcast LDS.64 per use

        // rolling rows: A = (x[w-1],x[w]) pair, B = (x[w+1],x[w+2]) pair
        ull uA = *(const ull*)(bp0);
        ull uB = *(const ull*)(bp0 + 2);
        ull mA = *(const ull*)(bp0 + SST);
        ull mB = *(const ull*)(bp0 + SST + 2);
#pragma unroll
        for (int r2 = 0; r2 < RR; ++r2) {
            const float* rp = bp0 + (r2 + 2) * SST;
            ull dA = *(const ull*)rp;
            ull dB = *(const ull*)(rp + 2);
            ull Cm = (mA >> 32) | (mB << 32);   // (x[w], x[w+1]) center pair
#pragma unroll
            for (int o = 0; o < On; ++o) {
                fma2(acc[r2][o], wp[0 * On + o], uB);  // NE: x(h-1, w+1..w+2)
                fma2(acc[r2][o], wp[1 * On + o], uA);  // NW: x(h-1, w-1..w)
                fma2(acc[r2][o], wp[2 * On + o], dB);  // SE: x(h+1, w+1..w+2)
                fma2(acc[r2][o], wp[3 * On + o], dA);  // SW: x(h+1, w-1..w)
                fma2(acc[r2][o], wp[4 * On + o], Cm);  // C : x(h,   w..w+1)
            }
            uA = mA; uB = mB; mA = dA; mB = dB;
        }
    }

    // epilogue: write y, accumulate BN stats
    float s[On] = {0, 0, 0, 0}, q[On] = {0, 0, 0, 0};
    const int wcol = bxw * TW + lw;
#pragma unroll
    for (int r2 = 0; r2 < RR; ++r2) {
        int h = byh * TH + i0 + r2;
#pragma unroll
        for (int o = 0; o < On; ++o) {
            float2 y = unpack2(acc[r2][o]);
            *(float2*)(out + (((size_t)(bz * On + o)) * Hn + h) * Wn + wcol) = y;
            s[o] += y.x + y.y;
            q[o] += y.x * y.x + y.y * y.y;
        }
    }
#pragma unroll
    for (int o = 0; o < On; ++o) {
        for (int offs = 16; offs; offs >>= 1) {
            s[o] += __shfl_xor_sync(0xffffffffu, s[o], offs);
            q[o] += __shfl_xor_sync(0xffffffffu, q[o], offs);
        }
    }
    if ((tid & 31) == 0) {
#pragma unroll
        for (int o = 0; o < On; ++o) {
            atomicAdd(&s_red[o], s[o]);
            atomicAdd(&s_red[On + o], q[o]);
        }
    }
    __syncthreads();
    if (tid < 2 * On) atomicAdd(&g_stats[tid], (double)s_red[tid]);
}

// ---------------------------------------------------------------------------
// Pass 2: normalize d_out in place. Each thread owns 4 float4s (MLP=4).
// BN scale/bias derived per-block from g_stats (stream order makes it final).
// ---------------------------------------------------------------------------
#define BN_ILP 4
__global__ __launch_bounds__(256)
void apply_bn(float4* __restrict__ y)
{
    __shared__ float s_sc[On], s_bi[On];
    if (threadIdx.x < On) {
        int o = threadIdx.x;
        const double N = (double)Bn * Hn * Wn;
        double mean = g_stats[o] / N;
        double var  = g_stats[On + o] / N - mean * mean;
        float sc = (float)(1.0 / sqrt(var + (double)BN_EPS));
        // gamma=1, beta=0 folded in by caller via g_gb; see below (passed via y? no)
        s_sc[o] = sc;
        s_bi[o] = (float)(-mean) * sc;
    }
    __syncthreads();

    int base = (blockIdx.x * 256 + threadIdx.x) * BN_ILP;
    float4 r[BN_ILP];
#pragma unroll
    for (int j = 0; j < BN_ILP; ++j) r[j] = y[base + j];
#pragma unroll
    for (int j = 0; j < BN_ILP; ++j) {
        int c = ((base + j) >> 16) & 3;       // 65536 float4 per (b,o) plane
        float sc = s_sc[c], bi = s_bi[c];
        r[j].x = r[j].x * sc + bi;
        r[j].y = r[j].y * sc + bi;
        r[j].z = r[j].z * sc + bi;
        r[j].w = r[j].w * sc + bi;
    }
#pragma unroll
    for (int j = 0; j < BN_ILP; ++j) y[base + j] = r[j];
}

// gamma/beta variant kept general: fold gamma/beta into stats-derived scale.
__global__ void fold_gamma_beta(const float* __restrict__ gamma,
                                const float* __restrict__ beta)
{
    // Fold gamma/beta into g_stats-space is not possible directly; instead we
    // rescale stats so apply_bn's (scale,bias) includes gamma/beta:
    //   y' = (y-mean)*rsqrt(var+eps)*gamma + beta
    // apply_bn computes sc=rsqrt(var+eps), bi=-mean*sc. We adjust by writing
    // adjusted stats is messy; simplest: stash gamma/beta in g_stats tail? No.
    // Instead: multiply handled here by updating a device array.
}

__device__ float g_gamma[On], g_beta[On];

__global__ void copy_gb(const float* __restrict__ gamma,
                        const float* __restrict__ beta)
{
    if (threadIdx.x < On) {
        g_gamma[threadIdx.x] = gamma[threadIdx.x];
        g_beta[threadIdx.x]  = beta[threadIdx.x];
    }
}

// Final apply_bn including gamma/beta (replaces the one above at launch time)
__global__ __launch_bounds__(256)
void apply_bn_gb(float4* __restrict__ y)
{
    __shared__ float s_sc[On], s_bi[On];
    if (threadIdx.x < On) {
        int o = threadIdx.x;
        const double N = (double)Bn * Hn * Wn;
        double mean = g_stats[o] / N;
        double var  = g_stats[On + o] / N - mean * mean;
        float r = (float)(1.0 / sqrt(var + (double)BN_EPS));
        float sc = g_gamma[o] * r;
        s_sc[o] = sc;
        s_bi[o] = g_beta[o] - (float)mean * sc;
    }
    __syncthreads();

    int base = (blockIdx.x * 256 + threadIdx.x) * BN_ILP;
    float4 r[BN_ILP];
#pragma unroll
    for (int j = 0; j < BN_ILP; ++j) r[j] = y[base + j];
#pragma unroll
    for (int j = 0; j < BN_ILP; ++j) {
        int c = ((base + j) >> 16) & 3;
        float sc = s_sc[c], bi = s_bi[c];
        r[j].x = r[j].x * sc + bi;
        r[j].y = r[j].y * sc + bi;
        r[j].z = r[j].z * sc + bi;
        r[j].w = r[j].w * sc + bi;
    }
#pragma unroll
    for (int j = 0; j < BN_ILP; ++j) y[base + j] = r[j];
}

extern "C" void kernel_launch(void* const* d_in, const int* in_sizes, int n_in,
                              void* d_out, int out_size)
{
    const float* x     = (const float*)d_in[0];
    const float* w     = (const float*)d_in[1];
    const float* gamma = (const float*)d_in[2];
    const float* beta  = (const float*)d_in[3];
    float* out = (float*)d_out;

    zero_stats_kernel<<<1, 32>>>();
    copy_gb<<<1, 32>>>(gamma, beta);

    dim3 grid(Wn / TW, Hn / TH, Bn);   // (8, 16, 8) = 1024 blocks
    fourdir_main<<<grid, NTHREADS>>>(x, w, out);

    int n4 = Bn * On * Hn * Wn / 4;    // 2,097,152 float4s
    apply_bn_gb<<<n4 / (256 * BN_ILP), 256>>>((float4*)out);
}